// round 1
// baseline (speedup 1.0000x reference)
#include <cuda_runtime.h>

// ---------------------------------------------------------------------------
// UniversalNeuralNetwork: 6 fused GEMM layers [32768x256]x[256x256] + bias +
// relu/tanh, with the "universal layer" quantum term collapsed analytically:
//   p[j] = (1/256) * prod_{d=0..8, g=0..2} cos^2(u_w[d, j, g])
// (the circulant update preserves row-uniform state, so the roll terms are
//  exactly zero and the scan reduces to a product of cosines).
//
// Strategy (round 1 baseline): fully fused persistent-tile kernel.
//  - 512 CTAs x 256 threads; each CTA owns a 64-row tile of the batch.
//  - h ping-pongs between two 64KB smem buffers (layout [row][k]); weights
//    stream L2->smem in 32-row chunks with register prefetch.
//  - fp32 math via Blackwell packed fma.rn.f32x2 (2x scalar FFMA rate).
// ---------------------------------------------------------------------------

#define DD      256
#define TM      64
#define KC      32
#define NCHUNK  (DD / KC)          // 8
#define NTHREADS 256
#define SMEM_BYTES ((2 * TM * DD + KC * DD) * 4)   // 160 KB

typedef unsigned long long u64;

__device__ __forceinline__ void ffma2(u64& d, u64 a, u64 b) {
    asm("fma.rn.f32x2 %0, %1, %2, %0;" : "+l"(d) : "l"(a), "l"(b));
}
__device__ __forceinline__ u64 dup2(float a) {
    u64 r; asm("mov.b64 %0, {%1, %1};" : "=l"(r) : "f"(a)); return r;
}
__device__ __forceinline__ float2 unpack2(u64 v) {
    float2 r; asm("mov.b64 {%0, %1}, %2;" : "=f"(r.x), "=f"(r.y) : "l"(v)); return r;
}

// p-vectors for the two universal layers: d_p[0..255] = u1, d_p[256..511] = u2
__device__ float d_p[2 * DD];

__global__ void pkern(const float* __restrict__ u1w, const float* __restrict__ u2w) {
    int t = threadIdx.x;
    const float* w = (t < DD) ? u1w : u2w;
    int j = t & (DD - 1);
    float prod = 1.0f / (float)DD;
    #pragma unroll
    for (int d = 0; d < 9; ++d) {
        #pragma unroll
        for (int g = 0; g < 3; ++g) {
            float c = cosf(w[(d * DD + j) * DD + g]);
            prod *= c * c;
        }
    }
    d_p[t] = prod;
}

__global__ void __launch_bounds__(NTHREADS, 1)
fused_mlp(const float* __restrict__ x,
          const float* __restrict__ w0, const float* __restrict__ b0,
          const float* __restrict__ w1, const float* __restrict__ b1,
          const float* __restrict__ u1cw, const float* __restrict__ u1cb,
          const float* __restrict__ w2, const float* __restrict__ b2,
          const float* __restrict__ u2cw, const float* __restrict__ u2cb,
          const float* __restrict__ wo, const float* __restrict__ bo,
          float* __restrict__ out)
{
    extern __shared__ float smem[];
    float* Abuf0 = smem;                    // [TM][DD]
    float* Abuf1 = smem + TM * DD;          // [TM][DD]
    float* Bs    = smem + 2 * TM * DD;      // [KC][DD]

    const int t    = threadIdx.x;
    const int tcol = t & 31;
    const int trow = t >> 5;
    const int r0   = trow * 8;
    const int row_base = blockIdx.x * TM;
    const int jlo  = 4 * tcol;
    const int jhi  = 128 + 4 * tcol;

    // ---- load x tile into Abuf0, layout [row][k] (coalesced float4) ----
    {
        const float4* xg = (const float4*)(x + (size_t)row_base * DD);
        float4* As = (float4*)Abuf0;
        #pragma unroll
        for (int i = 0; i < (TM * DD / 4) / NTHREADS; ++i)   // 16 iters
            As[t + i * NTHREADS] = xg[t + i * NTHREADS];
    }

    const float* Ws[6]  = { w0, w1, u1cw, w2, u2cw, wo };
    const float* Bv[6]  = { b0, b1, u1cb, b2, u2cb, bo };

    for (int L = 0; L < 6; ++L) {
        const float* W      = Ws[L];
        const bool   direct = (L == 2 || L == 4);   // h @ W (universal classical)
        const bool   is_tanh = direct;
        const bool   last   = (L == 5);
        const float* Asrc = (L & 1) ? Abuf1 : Abuf0;
        float*       Adst = (L & 1) ? Abuf0 : Abuf1;

        u64 acc[8][4];
        #pragma unroll
        for (int r = 0; r < 8; ++r)
            #pragma unroll
            for (int c = 0; c < 4; ++c) acc[r][c] = 0ull;

        // prefetch weight chunk 0 into registers
        float4 pf[8];
        if (direct) {
            #pragma unroll
            for (int i = 0; i < 8; ++i) {
                int lin = i * 1024 + t * 4;              // ki*256 + j
                pf[i] = *(const float4*)&W[lin];
            }
        } else {
            #pragma unroll
            for (int i = 0; i < 8; ++i)
                pf[i] = *(const float4*)&W[(size_t)t * DD + 4 * i];
        }

        for (int ch = 0; ch < NCHUNK; ++ch) {
            __syncthreads();   // previous chunk's compute (or prev layer) done
            // stage prefetched chunk into Bs:  Bs[ki][j]
            if (direct) {
                #pragma unroll
                for (int i = 0; i < 8; ++i) {
                    int lin = i * 1024 + t * 4;
                    *(float4*)&Bs[lin] = pf[i];
                }
            } else {
                // transpose store: Bs[ki][j=t] = W[t][kbase+ki]
                #pragma unroll
                for (int i = 0; i < 8; ++i) {
                    Bs[(4 * i + 0) * DD + t] = pf[i].x;
                    Bs[(4 * i + 1) * DD + t] = pf[i].y;
                    Bs[(4 * i + 2) * DD + t] = pf[i].z;
                    Bs[(4 * i + 3) * DD + t] = pf[i].w;
                }
            }
            __syncthreads();
            // prefetch next chunk (fully hidden under this chunk's compute)
            if (ch + 1 < NCHUNK) {
                int kb = (ch + 1) * KC;
                if (direct) {
                    #pragma unroll
                    for (int i = 0; i < 8; ++i) {
                        int lin = i * 1024 + t * 4;
                        pf[i] = *(const float4*)&W[(size_t)kb * DD + lin];
                    }
                } else {
                    #pragma unroll
                    for (int i = 0; i < 8; ++i)
                        pf[i] = *(const float4*)&W[(size_t)t * DD + kb + 4 * i];
                }
            }

            // ---- GEMM micro-kernel over this k-chunk ----
            const float* Arow = Asrc + r0 * DD + ch * KC;
            #pragma unroll 4
            for (int kk = 0; kk < KC / 2; ++kk) {
                const int k = 2 * kk;
                u64 bl0 = *(const u64*)&Bs[k * DD + jlo];
                u64 bl1 = *(const u64*)&Bs[k * DD + jlo + 2];
                u64 bh0 = *(const u64*)&Bs[k * DD + jhi];
                u64 bh1 = *(const u64*)&Bs[k * DD + jhi + 2];
                u64 cl0 = *(const u64*)&Bs[(k + 1) * DD + jlo];
                u64 cl1 = *(const u64*)&Bs[(k + 1) * DD + jlo + 2];
                u64 ch0 = *(const u64*)&Bs[(k + 1) * DD + jhi];
                u64 ch1 = *(const u64*)&Bs[(k + 1) * DD + jhi + 2];
                #pragma unroll
                for (int r = 0; r < 8; ++r) {
                    float2 a = *(const float2*)&Arow[r * DD + k];  // warp broadcast
                    u64 ax = dup2(a.x);
                    ffma2(acc[r][0], ax, bl0);
                    ffma2(acc[r][1], ax, bl1);
                    ffma2(acc[r][2], ax, bh0);
                    ffma2(acc[r][3], ax, bh1);
                    u64 ay = dup2(a.y);
                    ffma2(acc[r][0], ay, cl0);
                    ffma2(acc[r][1], ay, cl1);
                    ffma2(acc[r][2], ay, ch0);
                    ffma2(acc[r][3], ay, ch1);
                }
            }
        }

        // ---- epilogue: bias + activation, write to Adst (or gmem if last) ----
        float4 bia_l = *(const float4*)&Bv[L][jlo];
        float4 bia_h = *(const float4*)&Bv[L][jhi];
        float4 p_l = make_float4(0.f, 0.f, 0.f, 0.f);
        float4 p_h = p_l;
        if (is_tanh) {
            const float* pv = d_p + (L == 2 ? 0 : DD);
            p_l = *(const float4*)&pv[jlo];
            p_h = *(const float4*)&pv[jhi];
        }
        #pragma unroll
        for (int r = 0; r < 8; ++r) {
            float2 v0 = unpack2(acc[r][0]);
            float2 v1 = unpack2(acc[r][1]);
            float2 v2 = unpack2(acc[r][2]);
            float2 v3 = unpack2(acc[r][3]);
            float4 lo = make_float4(v0.x + bia_l.x, v0.y + bia_l.y,
                                    v1.x + bia_l.z, v1.y + bia_l.w);
            float4 hi = make_float4(v2.x + bia_h.x, v2.y + bia_h.y,
                                    v3.x + bia_h.z, v3.y + bia_h.w);
            if (is_tanh) {
                lo.x = tanhf(lo.x + p_l.x);  lo.y = tanhf(lo.y + p_l.y);
                lo.z = tanhf(lo.z + p_l.z);  lo.w = tanhf(lo.w + p_l.w);
                hi.x = tanhf(hi.x + p_h.x);  hi.y = tanhf(hi.y + p_h.y);
                hi.z = tanhf(hi.z + p_h.z);  hi.w = tanhf(hi.w + p_h.w);
            } else {
                lo.x = fmaxf(lo.x, 0.f);  lo.y = fmaxf(lo.y, 0.f);
                lo.z = fmaxf(lo.z, 0.f);  lo.w = fmaxf(lo.w, 0.f);
                hi.x = fmaxf(hi.x, 0.f);  hi.y = fmaxf(hi.y, 0.f);
                hi.z = fmaxf(hi.z, 0.f);  hi.w = fmaxf(hi.w, 0.f);
            }
            if (last) {
                float4* orow = (float4*)&out[(size_t)(row_base + r0 + r) * DD];
                orow[tcol]      = lo;
                orow[32 + tcol] = hi;
            } else {
                float4* orow = (float4*)&Adst[(r0 + r) * DD];
                orow[tcol]      = lo;
                orow[32 + tcol] = hi;
            }
        }
        // next layer's first __syncthreads() orders epilogue stores vs reads
    }
}

extern "C" void kernel_launch(void* const* d_in, const int* in_sizes, int n_in,
                              void* d_out, int out_size) {
    (void)in_sizes; (void)n_in; (void)out_size;
    const float* x     = (const float*)d_in[0];
    const float* w0    = (const float*)d_in[1];
    const float* b0    = (const float*)d_in[2];
    const float* w1    = (const float*)d_in[3];
    const float* b1    = (const float*)d_in[4];
    const float* u1w   = (const float*)d_in[5];
    const float* u1cw  = (const float*)d_in[6];
    const float* u1cb  = (const float*)d_in[7];
    const float* w2    = (const float*)d_in[8];
    const float* b2    = (const float*)d_in[9];
    const float* u2w   = (const float*)d_in[10];
    const float* u2cw  = (const float*)d_in[11];
    const float* u2cb  = (const float*)d_in[12];
    const float* wo    = (const float*)d_in[13];
    const float* bo    = (const float*)d_in[14];
    float* out = (float*)d_out;

    cudaFuncSetAttribute(fused_mlp, cudaFuncAttributeMaxDynamicSharedMemorySize,
                         SMEM_BYTES);

    pkern<<<1, 2 * DD>>>(u1w, u2w);
    fused_mlp<<<32768 / TM, NTHREADS, SMEM_BYTES>>>(
        x, w0, b0, w1, b1, u1cw, u1cb, w2, b2, u2cw, u2cb, wo, bo, out);
}

// round 2
// speedup vs baseline: 1.0559x; 1.0559x over previous
#include <cuda_runtime.h>

// ---------------------------------------------------------------------------
// UniversalNeuralNetwork: 6 fused GEMM layers [32768x256]x[256x256] + bias +
// relu/tanh, with the "universal layer" quantum term collapsed analytically:
//   p[j] = (1/256) * prod_{d=0..8, g=0..2} cos^2(u_w[d, j, g])
// (the circulant update preserves row-uniform state, so the roll terms are
//  exactly zero and the scan reduces to a product of cosines).
//
// Strategy (round 1 baseline): fully fused persistent-tile kernel.
//  - 512 CTAs x 256 threads; each CTA owns a 64-row tile of the batch.
//  - h ping-pongs between two 64KB smem buffers (layout [row][k]); weights
//    stream L2->smem in 32-row chunks with register prefetch.
//  - fp32 math via Blackwell packed fma.rn.f32x2 (2x scalar FFMA rate).
// ---------------------------------------------------------------------------

#define DD      256
#define TM      64
#define KC      32
#define NCHUNK  (DD / KC)          // 8
#define NTHREADS 256
#define SMEM_BYTES ((2 * TM * DD + KC * DD) * 4)   // 160 KB

typedef unsigned long long u64;

__device__ __forceinline__ void ffma2(u64& d, u64 a, u64 b) {
    asm("fma.rn.f32x2 %0, %1, %2, %0;" : "+l"(d) : "l"(a), "l"(b));
}
__device__ __forceinline__ u64 dup2(float a) {
    u64 r; asm("mov.b64 %0, {%1, %1};" : "=l"(r) : "f"(a)); return r;
}
__device__ __forceinline__ float2 unpack2(u64 v) {
    float2 r; asm("mov.b64 {%0, %1}, %2;" : "=f"(r.x), "=f"(r.y) : "l"(v)); return r;
}

// p-vectors for the two universal layers: d_p[0..255] = u1, d_p[256..511] = u2
__device__ float d_p[2 * DD];

__global__ void pkern(const float* __restrict__ u1w, const float* __restrict__ u2w) {
    int t = threadIdx.x;
    const float* w = (t < DD) ? u1w : u2w;
    int j = t & (DD - 1);
    float prod = 1.0f / (float)DD;
    #pragma unroll
    for (int d = 0; d < 9; ++d) {
        #pragma unroll
        for (int g = 0; g < 3; ++g) {
            float c = cosf(w[(d * DD + j) * DD + g]);
            prod *= c * c;
        }
    }
    d_p[t] = prod;
}

__global__ void __launch_bounds__(NTHREADS, 1)
fused_mlp(const float* __restrict__ x,
          const float* __restrict__ w0, const float* __restrict__ b0,
          const float* __restrict__ w1, const float* __restrict__ b1,
          const float* __restrict__ u1cw, const float* __restrict__ u1cb,
          const float* __restrict__ w2, const float* __restrict__ b2,
          const float* __restrict__ u2cw, const float* __restrict__ u2cb,
          const float* __restrict__ wo, const float* __restrict__ bo,
          float* __restrict__ out)
{
    extern __shared__ float smem[];
    float* Abuf0 = smem;                    // [TM][DD]
    float* Abuf1 = smem + TM * DD;          // [TM][DD]
    float* Bs    = smem + 2 * TM * DD;      // [KC][DD]

    const int t    = threadIdx.x;
    const int tcol = t & 31;
    const int trow = t >> 5;
    const int r0   = trow * 8;
    const int row_base = blockIdx.x * TM;
    const int jlo  = 4 * tcol;
    const int jhi  = 128 + 4 * tcol;

    // ---- load x tile into Abuf0, layout [row][k] (coalesced float4) ----
    {
        const float4* xg = (const float4*)(x + (size_t)row_base * DD);
        float4* As = (float4*)Abuf0;
        #pragma unroll
        for (int i = 0; i < (TM * DD / 4) / NTHREADS; ++i)   // 16 iters
            As[t + i * NTHREADS] = xg[t + i * NTHREADS];
    }

    const float* Ws[6]  = { w0, w1, u1cw, w2, u2cw, wo };
    const float* Bv[6]  = { b0, b1, u1cb, b2, u2cb, bo };

    for (int L = 0; L < 6; ++L) {
        const float* W      = Ws[L];
        const bool   direct = (L == 2 || L == 4);   // h @ W (universal classical)
        const bool   is_tanh = direct;
        const bool   last   = (L == 5);
        const float* Asrc = (L & 1) ? Abuf1 : Abuf0;
        float*       Adst = (L & 1) ? Abuf0 : Abuf1;

        u64 acc[8][4];
        #pragma unroll
        for (int r = 0; r < 8; ++r)
            #pragma unroll
            for (int c = 0; c < 4; ++c) acc[r][c] = 0ull;

        // prefetch weight chunk 0 into registers
        float4 pf[8];
        if (direct) {
            #pragma unroll
            for (int i = 0; i < 8; ++i) {
                int lin = i * 1024 + t * 4;              // ki*256 + j
                pf[i] = *(const float4*)&W[lin];
            }
        } else {
            #pragma unroll
            for (int i = 0; i < 8; ++i)
                pf[i] = *(const float4*)&W[(size_t)t * DD + 4 * i];
        }

        for (int ch = 0; ch < NCHUNK; ++ch) {
            __syncthreads();   // previous chunk's compute (or prev layer) done
            // stage prefetched chunk into Bs:  Bs[ki][j]
            if (direct) {
                #pragma unroll
                for (int i = 0; i < 8; ++i) {
                    int lin = i * 1024 + t * 4;
                    *(float4*)&Bs[lin] = pf[i];
                }
            } else {
                // transpose store: Bs[ki][j=t] = W[t][kbase+ki]
                #pragma unroll
                for (int i = 0; i < 8; ++i) {
                    Bs[(4 * i + 0) * DD + t] = pf[i].x;
                    Bs[(4 * i + 1) * DD + t] = pf[i].y;
                    Bs[(4 * i + 2) * DD + t] = pf[i].z;
                    Bs[(4 * i + 3) * DD + t] = pf[i].w;
                }
            }
            __syncthreads();
            // prefetch next chunk (fully hidden under this chunk's compute)
            if (ch + 1 < NCHUNK) {
                int kb = (ch + 1) * KC;
                if (direct) {
                    #pragma unroll
                    for (int i = 0; i < 8; ++i) {
                        int lin = i * 1024 + t * 4;
                        pf[i] = *(const float4*)&W[(size_t)kb * DD + lin];
                    }
                } else {
                    #pragma unroll
                    for (int i = 0; i < 8; ++i)
                        pf[i] = *(const float4*)&W[(size_t)t * DD + kb + 4 * i];
                }
            }

            // ---- GEMM micro-kernel over this k-chunk ----
            const float* Arow = Asrc + r0 * DD + ch * KC;
            #pragma unroll 4
            for (int kk = 0; kk < KC / 2; ++kk) {
                const int k = 2 * kk;
                u64 bl0 = *(const u64*)&Bs[k * DD + jlo];
                u64 bl1 = *(const u64*)&Bs[k * DD + jlo + 2];
                u64 bh0 = *(const u64*)&Bs[k * DD + jhi];
                u64 bh1 = *(const u64*)&Bs[k * DD + jhi + 2];
                u64 cl0 = *(const u64*)&Bs[(k + 1) * DD + jlo];
                u64 cl1 = *(const u64*)&Bs[(k + 1) * DD + jlo + 2];
                u64 ch0 = *(const u64*)&Bs[(k + 1) * DD + jhi];
                u64 ch1 = *(const u64*)&Bs[(k + 1) * DD + jhi + 2];
                #pragma unroll
                for (int r = 0; r < 8; ++r) {
                    float2 a = *(const float2*)&Arow[r * DD + k];  // warp broadcast
                    u64 ax = dup2(a.x);
                    ffma2(acc[r][0], ax, bl0);
                    ffma2(acc[r][1], ax, bl1);
                    ffma2(acc[r][2], ax, bh0);
                    ffma2(acc[r][3], ax, bh1);
                    u64 ay = dup2(a.y);
                    ffma2(acc[r][0], ay, cl0);
                    ffma2(acc[r][1], ay, cl1);
                    ffma2(acc[r][2], ay, ch0);
                    ffma2(acc[r][3], ay, ch1);
                }
            }
        }

        // ---- epilogue: bias + activation, write to Adst (or gmem if last) ----
        float4 bia_l = *(const float4*)&Bv[L][jlo];
        float4 bia_h = *(const float4*)&Bv[L][jhi];
        float4 p_l = make_float4(0.f, 0.f, 0.f, 0.f);
        float4 p_h = p_l;
        if (is_tanh) {
            const float* pv = d_p + (L == 2 ? 0 : DD);
            p_l = *(const float4*)&pv[jlo];
            p_h = *(const float4*)&pv[jhi];
        }
        #pragma unroll
        for (int r = 0; r < 8; ++r) {
            float2 v0 = unpack2(acc[r][0]);
            float2 v1 = unpack2(acc[r][1]);
            float2 v2 = unpack2(acc[r][2]);
            float2 v3 = unpack2(acc[r][3]);
            float4 lo = make_float4(v0.x + bia_l.x, v0.y + bia_l.y,
                                    v1.x + bia_l.z, v1.y + bia_l.w);
            float4 hi = make_float4(v2.x + bia_h.x, v2.y + bia_h.y,
                                    v3.x + bia_h.z, v3.y + bia_h.w);
            if (is_tanh) {
                lo.x = tanhf(lo.x + p_l.x);  lo.y = tanhf(lo.y + p_l.y);
                lo.z = tanhf(lo.z + p_l.z);  lo.w = tanhf(lo.w + p_l.w);
                hi.x = tanhf(hi.x + p_h.x);  hi.y = tanhf(hi.y + p_h.y);
                hi.z = tanhf(hi.z + p_h.z);  hi.w = tanhf(hi.w + p_h.w);
            } else {
                lo.x = fmaxf(lo.x, 0.f);  lo.y = fmaxf(lo.y, 0.f);
                lo.z = fmaxf(lo.z, 0.f);  lo.w = fmaxf(lo.w, 0.f);
                hi.x = fmaxf(hi.x, 0.f);  hi.y = fmaxf(hi.y, 0.f);
                hi.z = fmaxf(hi.z, 0.f);  hi.w = fmaxf(hi.w, 0.f);
            }
            if (last) {
                float4* orow = (float4*)&out[(size_t)(row_base + r0 + r) * DD];
                orow[tcol]      = lo;
                orow[32 + tcol] = hi;
            } else {
                float4* orow = (float4*)&Adst[(r0 + r) * DD];
                orow[tcol]      = lo;
                orow[32 + tcol] = hi;
            }
        }
        // next layer's first __syncthreads() orders epilogue stores vs reads
    }
}

extern "C" void kernel_launch(void* const* d_in, const int* in_sizes, int n_in,
                              void* d_out, int out_size) {
    (void)in_sizes; (void)n_in; (void)out_size;
    const float* x     = (const float*)d_in[0];
    const float* w0    = (const float*)d_in[1];
    const float* b0    = (const float*)d_in[2];
    const float* w1    = (const float*)d_in[3];
    const float* b1    = (const float*)d_in[4];
    const float* u1w   = (const float*)d_in[5];
    const float* u1cw  = (const float*)d_in[6];
    const float* u1cb  = (const float*)d_in[7];
    const float* w2    = (const float*)d_in[8];
    const float* b2    = (const float*)d_in[9];
    const float* u2w   = (const float*)d_in[10];
    const float* u2cw  = (const float*)d_in[11];
    const float* u2cb  = (const float*)d_in[12];
    const float* wo    = (const float*)d_in[13];
    const float* bo    = (const float*)d_in[14];
    float* out = (float*)d_out;

    cudaFuncSetAttribute(fused_mlp, cudaFuncAttributeMaxDynamicSharedMemorySize,
                         SMEM_BYTES);

    pkern<<<1, 2 * DD>>>(u1w, u2w);
    fused_mlp<<<32768 / TM, NTHREADS, SMEM_BYTES>>>(
        x, w0, b0, w1, b1, u1cw, u1cb, w2, b2, u2cw, u2cb, wo, bo, out);
}

// round 5
// speedup vs baseline: 2.3091x; 2.1867x over previous
#include <cuda_runtime.h>
#include <cuda_bf16.h>
#include <cstdint>

typedef uint32_t u32; typedef unsigned short u16;

#define DD 256
#define TM 128
#define NCTA 256
#define NTHREADS 512

// ---- smem byte offsets ----
#define A_HI 0                      // [128][256] bf16, swizzled, 64KB
#define A_LO 65536                  // 64KB
#define BW_OFF 131072               // [2 buf][2 plane][256 rows * 48B]
#define BROW 48
#define BPLANE (256 * BROW)         // 12288
#define BBUF   (2 * BPLANE)         // 24576
#define BIAS_OFF (BW_OFF + 2 * BBUF)        // 180224 (6*256 floats)
#define PV_OFF   (BIAS_OFF + 6 * 256 * 4)   // 186368 (512 floats)
#define SMEM_TOTAL (PV_OFF + 512 * 4)       // 188416

// ---- device scratch ----
__device__ float d_p[2 * DD];
// [layer][plane hi/lo][k-chunk][n][k-within-chunk]
__device__ __align__(16) __nv_bfloat16 d_Bw[6][2][16][256][16];

// ---- helpers ----
__device__ __forceinline__ u32 smem_u32(const void* p) {
    u32 a;
    asm("{ .reg .u64 t; cvta.to.shared.u64 t, %1; cvt.u32.u64 %0, t; }" : "=r"(a) : "l"(p));
    return a;
}
__device__ __forceinline__ float fast_tanh(float x) {
    float e, r;
    asm("ex2.approx.f32 %0, %1;" : "=f"(e) : "f"(x * 2.8853900817779268f));
    asm("rcp.approx.f32 %0, %1;" : "=f"(r) : "f"(e + 1.0f));
    return 1.0f - 2.0f * r;
}
__device__ __forceinline__ void split2(float a, float b, u32& h, u32& l) {
    u16 ha = __bfloat16_as_ushort(__float2bfloat16_rn(a));
    u16 hb = __bfloat16_as_ushort(__float2bfloat16_rn(b));
    float fa = __bfloat162float(__ushort_as_bfloat16(ha));
    float fb = __bfloat162float(__ushort_as_bfloat16(hb));
    u16 la = __bfloat16_as_ushort(__float2bfloat16_rn(a - fa));
    u16 lb = __bfloat16_as_ushort(__float2bfloat16_rn(b - fb));
    h = ((u32)hb << 16) | ha;
    l = ((u32)lb << 16) | la;
}
// swizzled byte offset into an A plane: row stride 512B, 16B units XOR'd by row
__device__ __forceinline__ int aoff(int row, int col) {
    return row * 512 + ((((col >> 3) ^ (row & 7)) << 4) | ((col & 7) << 1));
}

#define LDSM4(r, addr) \
    asm volatile("ldmatrix.sync.aligned.m8n8.x4.shared.b16 {%0,%1,%2,%3}, [%4];" \
        : "=r"((r)[0]), "=r"((r)[1]), "=r"((r)[2]), "=r"((r)[3]) : "r"(addr))
#define MMA(d, a, b0, b1) \
    asm volatile("mma.sync.aligned.m16n8k16.row.col.f32.bf16.bf16.f32 " \
        "{%0,%1,%2,%3}, {%4,%5,%6,%7}, {%8,%9}, {%0,%1,%2,%3};" \
        : "+f"((d)[0]), "+f"((d)[1]), "+f"((d)[2]), "+f"((d)[3]) \
        : "r"((a)[0]), "r"((a)[1]), "r"((a)[2]), "r"((a)[3]), "r"(b0), "r"(b1))
#define CPASYNC16(dst, src) \
    asm volatile("cp.async.cg.shared.global [%0], [%1], 16;" :: "r"(dst), "l"(src))

// ---- prologue kernels ----
__global__ void pkern(const float* __restrict__ u1w, const float* __restrict__ u2w) {
    int t = threadIdx.x;
    const float* w = (t < DD) ? u1w : u2w;
    int j = t & (DD - 1);
    float prod = 1.0f / (float)DD;
    #pragma unroll
    for (int d = 0; d < 9; ++d)
        #pragma unroll
        for (int g = 0; g < 3; ++g) {
            float c = cosf(w[(d * DD + j) * DD + g]);
            prod *= c * c;
        }
    d_p[t] = prod;
}

__global__ void wprep(const float* __restrict__ w0, const float* __restrict__ w1,
                      const float* __restrict__ u1cw, const float* __restrict__ w2,
                      const float* __restrict__ u2cw, const float* __restrict__ wo) {
    int L = blockIdx.x >> 8, n = blockIdx.x & 255, k = threadIdx.x;
    const float* W; bool direct;
    switch (L) {
        case 0: W = w0;   direct = false; break;
        case 1: W = w1;   direct = false; break;
        case 2: W = u1cw; direct = true;  break;
        case 3: W = w2;   direct = false; break;
        case 4: W = u2cw; direct = true;  break;
        default: W = wo;  direct = false; break;
    }
    // B[n][k]: layers computing h @ W^T read W[n][k]; direct layers (h @ W) read W[k][n]
    float wv = direct ? W[k * DD + n] : W[n * DD + k];
    __nv_bfloat16 h = __float2bfloat16_rn(wv);
    __nv_bfloat16 l = __float2bfloat16_rn(wv - __bfloat162float(h));
    d_Bw[L][0][k >> 4][n][k & 15] = h;
    d_Bw[L][1][k >> 4][n][k & 15] = l;
}

// ---- main kernel ----
__global__ void __launch_bounds__(NTHREADS, 1)
mlp_mma(const float* __restrict__ x,
        const float* __restrict__ b0, const float* __restrict__ b1,
        const float* __restrict__ u1cb, const float* __restrict__ b2,
        const float* __restrict__ u2cb, const float* __restrict__ bo,
        float* __restrict__ out)
{
    extern __shared__ __align__(1024) unsigned char sm[];
    float* smf = (float*)sm;
    const u32 smb = smem_u32(sm);
    const int tid = threadIdx.x, lane = tid & 31, wid = tid >> 5;
    const int wm = wid & 3, wn = wid >> 2;
    const int mrow = wm * 32, ncol = wn * 64;

    // ---- issue weight chunk (L=0, ck=0) into buf 0 ----
    #pragma unroll
    for (int t = 0; t < 2; ++t) {
        int i = tid * 2 + t;                       // 0..1023
        int p = i >> 9, n = (i >> 1) & 255, j = i & 1;
        u32 dst = smb + BW_OFF + p * BPLANE + n * BROW + j * 16;
        CPASYNC16(dst, (const char*)&d_Bw[0][p][0][n][j * 8]);
    }
    asm volatile("cp.async.commit_group;");

    // ---- stage biases and p ----
    if (tid < 256) {
        const float* bs[6] = { b0, b1, u1cb, b2, u2cb, bo };
        #pragma unroll
        for (int L = 0; L < 6; ++L) smf[BIAS_OFF / 4 + L * 256 + tid] = bs[L][tid];
        smf[PV_OFF / 4 + tid]       = d_p[tid];
        smf[PV_OFF / 4 + 256 + tid] = d_p[256 + tid];
    }

    // ---- load x tile, split to bf16 hi/lo planes ----
    {
        const float* xb = x + (size_t)blockIdx.x * TM * DD;
        #pragma unroll
        for (int it = 0; it < 16; ++it) {
            int idx = it * NTHREADS + tid;         // 0..8191
            int row = idx >> 6, c0 = (idx & 63) * 4;
            float4 f = __ldg((const float4*)(xb + row * DD + c0));
            u32 h0, l0, h1, l1;
            split2(f.x, f.y, h0, l0);
            split2(f.z, f.w, h1, l1);
            int off = aoff(row, c0);
            *(uint2*)(sm + A_HI + off) = make_uint2(h0, h1);
            *(uint2*)(sm + A_LO + off) = make_uint2(l0, l1);
        }
    }

    for (int L = 0; L < 6; ++L) {
        float acc[2][8][4];
        #pragma unroll
        for (int mt = 0; mt < 2; ++mt)
            #pragma unroll
            for (int j = 0; j < 8; ++j)
                #pragma unroll
                for (int q = 0; q < 4; ++q) acc[mt][j][q] = 0.f;

        for (int ck = 0; ck < 16; ++ck) {
            __syncthreads();                       // prev chunk compute / A writes done
            bool issue = (ck < 15) || (L < 5);
            if (issue) {
                int nL = (ck < 15) ? L : L + 1;
                int nck = (ck < 15) ? ck + 1 : 0;
                int slot = (ck + 1) & 1;
                #pragma unroll
                for (int t = 0; t < 2; ++t) {
                    int i = tid * 2 + t;
                    int p = i >> 9, n = (i >> 1) & 255, j = i & 1;
                    u32 dst = smb + BW_OFF + slot * BBUF + p * BPLANE + n * BROW + j * 16;
                    CPASYNC16(dst, (const char*)&d_Bw[nL][p][nck][n][j * 8]);
                }
                asm volatile("cp.async.commit_group;");
                asm volatile("cp.async.wait_group 1;");
            } else {
                asm volatile("cp.async.wait_group 0;");
            }
            __syncthreads();                       // chunk ck resident for all

            const u32 bb = smb + BW_OFF + (ck & 1) * BBUF;
            // ---- B fragments for this warp's 64-col slab ----
            // B stored [n][k] with k contiguous -> NON-trans ldmatrix gives the
            // required fragment (n = lane>>2, k = 2*(lane&3)+{0,1}).
            u32 bh[16], bl[16];
            #pragma unroll
            for (int nt2 = 0; nt2 < 4; ++nt2) {
                int n0 = ncol + nt2 * 16;
                int nrow = n0 + (lane & 7) + ((lane >> 4) << 3);
                u32 ad = bb + nrow * BROW + (((lane >> 3) & 1) << 4);
                LDSM4(&bh[nt2 * 4], ad);
                LDSM4(&bl[nt2 * 4], ad + BPLANE);
            }
            // ---- A fragments + MMA ----
            #pragma unroll
            for (int mt = 0; mt < 2; ++mt) {
                int arow = mrow + mt * 16 + (lane & 15);
                int au = ck * 2 + (lane >> 4);
                u32 abase = arow * 512 + (((au ^ (arow & 7)) << 4));
                u32 a[4];
                LDSM4(a, smb + A_HI + abase);
                #pragma unroll
                for (int j = 0; j < 8; ++j) {
                    MMA(acc[mt][j], a, bh[2 * j], bh[2 * j + 1]);
                    MMA(acc[mt][j], a, bl[2 * j], bl[2 * j + 1]);
                }
                LDSM4(a, smb + A_LO + abase);
                #pragma unroll
                for (int j = 0; j < 8; ++j)
                    MMA(acc[mt][j], a, bh[2 * j], bh[2 * j + 1]);
            }
        }

        __syncthreads();                           // all A reads done before overwrite

        // ---- epilogue: bias + activation, write back (or to gmem) ----
        const float* bias = smf + BIAS_OFF / 4 + L * 256;
        const float* pv   = smf + PV_OFF / 4 + ((L == 2) ? 0 : 256);
        const bool ut = (L == 2 || L == 4);
        const int r1 = mrow + (lane >> 2);
        #pragma unroll
        for (int mt = 0; mt < 2; ++mt) {
            #pragma unroll
            for (int j = 0; j < 8; ++j) {
                int col = ncol + j * 8 + (lane & 3) * 2;
                float bx = bias[col], by = bias[col + 1];
                float v0 = acc[mt][j][0] + bx, v1 = acc[mt][j][1] + by;
                float v2 = acc[mt][j][2] + bx, v3 = acc[mt][j][3] + by;
                if (ut) {
                    float px = pv[col], py = pv[col + 1];
                    v0 = fast_tanh(v0 + px); v1 = fast_tanh(v1 + py);
                    v2 = fast_tanh(v2 + px); v3 = fast_tanh(v3 + py);
                } else {
                    v0 = fmaxf(v0, 0.f); v1 = fmaxf(v1, 0.f);
                    v2 = fmaxf(v2, 0.f); v3 = fmaxf(v3, 0.f);
                }
                int ra = r1 + mt * 16, rb = ra + 8;
                if (L == 5) {
                    size_t gra = (size_t)(blockIdx.x * TM + ra) * DD + col;
                    size_t grb = (size_t)(blockIdx.x * TM + rb) * DD + col;
                    *(float2*)(out + gra) = make_float2(v0, v1);
                    *(float2*)(out + grb) = make_float2(v2, v3);
                } else {
                    u32 h, l;
                    split2(v0, v1, h, l);
                    int oa = aoff(ra, col);
                    *(u32*)(sm + A_HI + oa) = h;
                    *(u32*)(sm + A_LO + oa) = l;
                    split2(v2, v3, h, l);
                    int ob = aoff(rb, col);
                    *(u32*)(sm + A_HI + ob) = h;
                    *(u32*)(sm + A_LO + ob) = l;
                }
            }
        }
        // next layer's first __syncthreads orders these writes vs. reads
    }
}

extern "C" void kernel_launch(void* const* d_in, const int* in_sizes, int n_in,
                              void* d_out, int out_size) {
    (void)in_sizes; (void)n_in; (void)out_size;
    const float* x    = (const float*)d_in[0];
    const float* w0   = (const float*)d_in[1];
    const float* b0   = (const float*)d_in[2];
    const float* w1   = (const float*)d_in[3];
    const float* b1   = (const float*)d_in[4];
    const float* u1w  = (const float*)d_in[5];
    const float* u1cw = (const float*)d_in[6];
    const float* u1cb = (const float*)d_in[7];
    const float* w2   = (const float*)d_in[8];
    const float* b2   = (const float*)d_in[9];
    const float* u2w  = (const float*)d_in[10];
    const float* u2cw = (const float*)d_in[11];
    const float* u2cb = (const float*)d_in[12];
    const float* wo   = (const float*)d_in[13];
    const float* bo   = (const float*)d_in[14];
    float* out = (float*)d_out;

    cudaFuncSetAttribute(mlp_mma, cudaFuncAttributeMaxDynamicSharedMemorySize, SMEM_TOTAL);

    pkern<<<1, 2 * DD>>>(u1w, u2w);
    wprep<<<6 * 256, 256>>>(w0, w1, u1cw, w2, u2cw, wo);
    mlp_mma<<<NCTA, NTHREADS, SMEM_TOTAL>>>(x, b0, b1, u1cb, b2, u2cb, bo, out);
}

// round 6
// speedup vs baseline: 2.3485x; 1.0171x over previous
#include <cuda_runtime.h>
#include <cuda_bf16.h>
#include <cstdint>

typedef uint32_t u32; typedef unsigned short u16;

#define DD 256
#define NCTA 148
#define NTHREADS 512

// ---- smem byte offsets ----
#define A_HI 0                      // [128][256] bf16, swizzled, 64KB
#define A_LO 65536                  // 64KB
#define BW_OFF 131072               // 3 slots x [2 plane][256 rows * 48B]
#define BROW 48
#define BPLANE (256 * BROW)         // 12288
#define BBUF   (2 * BPLANE)         // 24576 per slot
#define BIAS_OFF (BW_OFF + 3 * BBUF)        // 204800 (6*256 floats)
#define PV_OFF   (BIAS_OFF + 6 * 256 * 4)   // 210944 (512 floats)
#define SMEM_TOTAL (PV_OFF + 512 * 4)       // 212992 (208 KB)

// ---- device scratch ----
__device__ float d_p[2 * DD];
// [layer][plane hi/lo][k-chunk][n][k-within-chunk]
__device__ __align__(16) __nv_bfloat16 d_Bw[6][2][16][256][16];

// ---- helpers ----
__device__ __forceinline__ u32 smem_u32(const void* p) {
    u32 a;
    asm("{ .reg .u64 t; cvta.to.shared.u64 t, %1; cvt.u32.u64 %0, t; }" : "=r"(a) : "l"(p));
    return a;
}
__device__ __forceinline__ float fast_tanh(float x) {
    float e, r;
    asm("ex2.approx.f32 %0, %1;" : "=f"(e) : "f"(x * 2.8853900817779268f));
    asm("rcp.approx.f32 %0, %1;" : "=f"(r) : "f"(e + 1.0f));
    return 1.0f - 2.0f * r;
}
__device__ __forceinline__ void split2(float a, float b, u32& h, u32& l) {
    u16 ha = __bfloat16_as_ushort(__float2bfloat16_rn(a));
    u16 hb = __bfloat16_as_ushort(__float2bfloat16_rn(b));
    float fa = __bfloat162float(__ushort_as_bfloat16(ha));
    float fb = __bfloat162float(__ushort_as_bfloat16(hb));
    u16 la = __bfloat16_as_ushort(__float2bfloat16_rn(a - fa));
    u16 lb = __bfloat16_as_ushort(__float2bfloat16_rn(b - fb));
    h = ((u32)hb << 16) | ha;
    l = ((u32)lb << 16) | la;
}
// swizzled byte offset into an A plane: row stride 512B, 16B units XOR'd by row
__device__ __forceinline__ int aoff(int row, int col) {
    return row * 512 + ((((col >> 3) ^ (row & 7)) << 4) | ((col & 7) << 1));
}

#define LDSM4(r, addr) \
    asm volatile("ldmatrix.sync.aligned.m8n8.x4.shared.b16 {%0,%1,%2,%3}, [%4];" \
        : "=r"((r)[0]), "=r"((r)[1]), "=r"((r)[2]), "=r"((r)[3]) : "r"(addr))
#define MMA(d, a, b0, b1) \
    asm volatile("mma.sync.aligned.m16n8k16.row.col.f32.bf16.bf16.f32 " \
        "{%0,%1,%2,%3}, {%4,%5,%6,%7}, {%8,%9}, {%0,%1,%2,%3};" \
        : "+f"((d)[0]), "+f"((d)[1]), "+f"((d)[2]), "+f"((d)[3]) \
        : "r"((a)[0]), "r"((a)[1]), "r"((a)[2]), "r"((a)[3]), "r"(b0), "r"(b1))
#define CPASYNC16(dst, src) \
    asm volatile("cp.async.cg.shared.global [%0], [%1], 16;" :: "r"(dst), "l"(src))

// ---- fused prologue: weight split/reorder + p-vector ----
__global__ void prep(const float* __restrict__ w0, const float* __restrict__ w1,
                     const float* __restrict__ u1cw, const float* __restrict__ w2,
                     const float* __restrict__ u2cw, const float* __restrict__ wo,
                     const float* __restrict__ u1w, const float* __restrict__ u2w) {
    int b = blockIdx.x;
    if (b < 1536) {
        int L = b >> 8, n = b & 255, k = threadIdx.x;
        const float* W; bool direct;
        switch (L) {
            case 0: W = w0;   direct = false; break;
            case 1: W = w1;   direct = false; break;
            case 2: W = u1cw; direct = true;  break;
            case 3: W = w2;   direct = false; break;
            case 4: W = u2cw; direct = true;  break;
            default: W = wo;  direct = false; break;
        }
        float wv = direct ? W[k * DD + n] : W[n * DD + k];
        __nv_bfloat16 h = __float2bfloat16_rn(wv);
        __nv_bfloat16 l = __float2bfloat16_rn(wv - __bfloat162float(h));
        d_Bw[L][0][k >> 4][n][k & 15] = h;
        d_Bw[L][1][k >> 4][n][k & 15] = l;
    } else {
        int t = (b - 1536) * 256 + threadIdx.x;    // 0..511
        const float* w = (t < DD) ? u1w : u2w;
        int j = t & (DD - 1);
        float prod = 1.0f / (float)DD;
        #pragma unroll
        for (int d = 0; d < 9; ++d)
            #pragma unroll
            for (int g = 0; g < 3; ++g) {
                float c = cosf(w[(d * DD + j) * DD + g]);
                prod *= c * c;
            }
        d_p[t] = prod;
    }
}

// ---- main kernel ----
__global__ void __launch_bounds__(NTHREADS, 1)
mlp_mma(const float* __restrict__ x,
        const float* __restrict__ b0, const float* __restrict__ b1,
        const float* __restrict__ u1cb, const float* __restrict__ b2,
        const float* __restrict__ u2cb, const float* __restrict__ bo,
        float* __restrict__ out)
{
    extern __shared__ __align__(1024) unsigned char sm[];
    float* smf = (float*)sm;
    const u32 smb = smem_u32(sm);
    const int tid = threadIdx.x, lane = tid & 31, wid = tid >> 5;
    const int wm = wid & 3, wn = wid >> 2;
    const int mrow = wm * 32, ncol = wn * 64;

    // ---- stage biases and p ----
    if (tid < 256) {
        const float* bs[6] = { b0, b1, u1cb, b2, u2cb, bo };
        #pragma unroll
        for (int L = 0; L < 6; ++L) smf[BIAS_OFF / 4 + L * 256 + tid] = bs[L][tid];
        smf[PV_OFF / 4 + tid]       = d_p[tid];
        smf[PV_OFF / 4 + 256 + tid] = d_p[256 + tid];
    }

    // row range for this CTA (8-aligned, balanced over 148 CTAs)
    const int r0g = (int)(((long long)blockIdx.x << 15) / NCTA) & ~7;
    const int r1g = (int)(((long long)(blockIdx.x + 1) << 15) / NCTA) & ~7;

    // per-thread cp.async destination pieces (same for every chunk)
    const int ci_p = (tid * 2) >> 9;            // plane of first copy
    // (two copies per thread: i = tid*2 and tid*2+1)

    for (int sub = 0; sub < 2; ++sub) {
        const int rbase = r0g + sub * 128;
        const int H     = sub ? 96 : 128;           // smem tile height
        const int real  = sub ? (r1g - r0g - 128) : 128;   // valid rows (88..96 / 128)
        const bool act  = (sub == 0) | (wm < 3);    // warps with real m-tiles

        // ---- prime ring: issue chunks 0 and 1 ----
        #pragma unroll
        for (int pg = 0; pg < 2; ++pg) {
            #pragma unroll
            for (int t = 0; t < 2; ++t) {
                int i = tid * 2 + t;
                int p = i >> 9, n = (i >> 1) & 255, j = i & 1;
                u32 dst = smb + BW_OFF + pg * BBUF + p * BPLANE + n * BROW + j * 16;
                CPASYNC16(dst, (const char*)&d_Bw[0][p][pg][n][j * 8]);
            }
            asm volatile("cp.async.commit_group;");
        }

        // ---- load x tile (zero-padded), split to bf16 hi/lo planes ----
        {
            const int iters = (H * 64) / NTHREADS;     // 16 or 12
            for (int it = 0; it < iters; ++it) {
                int idx = it * NTHREADS + tid;
                int row = idx >> 6, c0 = (idx & 63) * 4;
                float4 f = make_float4(0.f, 0.f, 0.f, 0.f);
                if (row < real)
                    f = __ldg((const float4*)(x + (size_t)(rbase + row) * DD + c0));
                u32 h0, l0, h1, l1;
                split2(f.x, f.y, h0, l0);
                split2(f.z, f.w, h1, l1);
                int off = aoff(row, c0);
                *(uint2*)(sm + A_HI + off) = make_uint2(h0, h1);
                *(uint2*)(sm + A_LO + off) = make_uint2(l0, l1);
            }
        }

        for (int L = 0; L < 6; ++L) {
            float acc[2][8][4];
            #pragma unroll
            for (int mt = 0; mt < 2; ++mt)
                #pragma unroll
                for (int j = 0; j < 8; ++j)
                    #pragma unroll
                    for (int q = 0; q < 4; ++q) acc[mt][j][q] = 0.f;

            for (int ck = 0; ck < 16; ++ck) {
                const int g = L * 16 + ck;
                // chunk g landed (own thread's copies)
                if (g < 95) asm volatile("cp.async.wait_group 1;");
                else        asm volatile("cp.async.wait_group 0;");
                // all threads waited (chunk g visible) AND all done with chunk g-1
                __syncthreads();
                // refill slot (g+2)%3 (= slot of g-1, now safe to overwrite)
                if (g + 2 < 96) {
                    const int g2 = g + 2;
                    const int s2 = g2 % 3, nL = g2 >> 4, nck = g2 & 15;
                    #pragma unroll
                    for (int t = 0; t < 2; ++t) {
                        int i = tid * 2 + t;
                        int p = i >> 9, n = (i >> 1) & 255, j = i & 1;
                        u32 dst = smb + BW_OFF + s2 * BBUF + p * BPLANE + n * BROW + j * 16;
                        CPASYNC16(dst, (const char*)&d_Bw[nL][p][nck][n][j * 8]);
                    }
                    asm volatile("cp.async.commit_group;");
                }

                if (act) {
                    const u32 bb = smb + BW_OFF + (g % 3) * BBUF;
                    // B fragments (non-trans ldmatrix on [n][k] layout)
                    u32 bh[16], bl[16];
                    #pragma unroll
                    for (int nt2 = 0; nt2 < 4; ++nt2) {
                        int n0 = ncol + nt2 * 16;
                        int nrow = n0 + (lane & 7) + ((lane >> 4) << 3);
                        u32 ad = bb + nrow * BROW + (((lane >> 3) & 1) << 4);
                        LDSM4(&bh[nt2 * 4], ad);
                        LDSM4(&bl[nt2 * 4], ad + BPLANE);
                    }
                    // A fragments + MMA (3-pass bf16 split)
                    #pragma unroll
                    for (int mt = 0; mt < 2; ++mt) {
                        int arow = mrow + mt * 16 + (lane & 15);
                        int au = ck * 2 + (lane >> 4);
                        u32 abase = arow * 512 + (((au ^ (arow & 7)) << 4));
                        u32 a[4];
                        LDSM4(a, smb + A_HI + abase);
                        #pragma unroll
                        for (int j = 0; j < 8; ++j) {
                            MMA(acc[mt][j], a, bh[2 * j], bh[2 * j + 1]);
                            MMA(acc[mt][j], a, bl[2 * j], bl[2 * j + 1]);
                        }
                        LDSM4(a, smb + A_LO + abase);
                        #pragma unroll
                        for (int j = 0; j < 8; ++j)
                            MMA(acc[mt][j], a, bh[2 * j], bh[2 * j + 1]);
                    }
                }
            }

            __syncthreads();       // all compute done before A overwrite

            // ---- epilogue: bias + activation ----
            if (act) {
                const float* bias = smf + BIAS_OFF / 4 + L * 256;
                const float* pv   = smf + PV_OFF / 4 + ((L == 2) ? 0 : 256);
                const bool ut = (L == 2 || L == 4);
                const int r1 = mrow + (lane >> 2);
                #pragma unroll
                for (int mt = 0; mt < 2; ++mt) {
                    #pragma unroll
                    for (int j = 0; j < 8; ++j) {
                        int col = ncol + j * 8 + (lane & 3) * 2;
                        float bx = bias[col], by = bias[col + 1];
                        float v0 = acc[mt][j][0] + bx, v1 = acc[mt][j][1] + by;
                        float v2 = acc[mt][j][2] + bx, v3 = acc[mt][j][3] + by;
                        if (ut) {
                            float px = pv[col], py = pv[col + 1];
                            v0 = fast_tanh(v0 + px); v1 = fast_tanh(v1 + py);
                            v2 = fast_tanh(v2 + px); v3 = fast_tanh(v3 + py);
                        } else {
                            v0 = fmaxf(v0, 0.f); v1 = fmaxf(v1, 0.f);
                            v2 = fmaxf(v2, 0.f); v3 = fmaxf(v3, 0.f);
                        }
                        int ra = r1 + mt * 16, rb = ra + 8;
                        if (L == 5) {
                            if (ra < real) {
                                *(float2*)(out + (size_t)(rbase + ra) * DD + col)
                                    = make_float2(v0, v1);
                            }
                            if (rb < real) {
                                *(float2*)(out + (size_t)(rbase + rb) * DD + col)
                                    = make_float2(v2, v3);
                            }
                        } else {
                            u32 h, l;
                            split2(v0, v1, h, l);
                            int oa = aoff(ra, col);
                            *(u32*)(sm + A_HI + oa) = h;
                            *(u32*)(sm + A_LO + oa) = l;
                            split2(v2, v3, h, l);
                            int ob = aoff(rb, col);
                            *(u32*)(sm + A_HI + ob) = h;
                            *(u32*)(sm + A_LO + ob) = l;
                        }
                    }
                }
            }
            // next chunk-loop's first __syncthreads orders epilogue writes vs reads
        }
    }
}

extern "C" void kernel_launch(void* const* d_in, const int* in_sizes, int n_in,
                              void* d_out, int out_size) {
    (void)in_sizes; (void)n_in; (void)out_size;
    const float* x    = (const float*)d_in[0];
    const float* w0   = (const float*)d_in[1];
    const float* b0   = (const float*)d_in[2];
    const float* w1   = (const float*)d_in[3];
    const float* b1   = (const float*)d_in[4];
    const float* u1w  = (const float*)d_in[5];
    const float* u1cw = (const float*)d_in[6];
    const float* u1cb = (const float*)d_in[7];
    const float* w2   = (const float*)d_in[8];
    const float* b2   = (const float*)d_in[9];
    const float* u2w  = (const float*)d_in[10];
    const float* u2cw = (const float*)d_in[11];
    const float* u2cb = (const float*)d_in[12];
    const float* wo   = (const float*)d_in[13];
    const float* bo   = (const float*)d_in[14];
    float* out = (float*)d_out;

    cudaFuncSetAttribute(mlp_mma, cudaFuncAttributeMaxDynamicSharedMemorySize, SMEM_TOTAL);

    prep<<<1538, 256>>>(w0, w1, u1cw, w2, u2cw, wo, u1w, u2w);
    mlp_mma<<<NCTA, NTHREADS, SMEM_TOTAL>>>(x, b0, b1, u1cb, b2, u2cb, bo, out);
}